// round 3
// baseline (speedup 1.0000x reference)
#include <cuda_runtime.h>

#define T_STEPS 50
#define NB 64   // blocks in the scan kernel; NB*4 = 256 = H

// ---------------- scratch (device globals; no allocation) ----------------
__device__ float    g_pre[T_STEPS * 768];   // pre_low[t][768] = Wih_low[:, :256]@x_t + bih_low
__device__ float    g_Lout[T_STEPS * 256];  // h1 per step (L_output)
__device__ float    g_h1[2][256];           // double-buffered low-cell state
__device__ float    g_h2[256];              // high-cell state
__device__ unsigned g_bar;                  // grid barrier counter

// ---------------- helpers ----------------
__device__ __forceinline__ float warpsum(float v) {
    v += __shfl_xor_sync(0xffffffffu, v, 16);
    v += __shfl_xor_sync(0xffffffffu, v, 8);
    v += __shfl_xor_sync(0xffffffffu, v, 4);
    v += __shfl_xor_sync(0xffffffffu, v, 2);
    v += __shfl_xor_sync(0xffffffffu, v, 1);
    return v;
}
__device__ __forceinline__ float eluf(float x) { return x > 0.f ? x : expm1f(x); }
__device__ __forceinline__ float sigf(float x) { return 1.f / (1.f + expf(-x)); }
__device__ __forceinline__ float dot4(float4 a, float4 b) {
    return a.x * b.x + a.y * b.y + a.z * b.z + a.w * b.w;
}

// ---------------- kernel 1: front-end MLP + pre_low + state init ----------------
__global__ void __launch_bounds__(256) k1_front(
    const float* __restrict__ v0,   // (T,1,768)
    const float* __restrict__ m0,   // (T,1,2)
    const float* __restrict__ W1v,  // (128,768)
    const float* __restrict__ b1v,  // (128)
    const float* __restrict__ W1m,  // (128,2)
    const float* __restrict__ b1m,  // (128)
    const float* __restrict__ WihL, // (768,512)
    const float* __restrict__ bihL) // (768)
{
    int t = blockIdx.x, tid = threadIdx.x, warp = tid >> 5, lane = tid & 31;
    __shared__ __align__(16) float xv[768];
    __shared__ __align__(16) float xc[256];

    for (int i = tid; i < 768; i += 256) xv[i] = v0[t * 768 + i];
    float ma = m0[t * 2 + 0], mb = m0[t * 2 + 1];
    __syncthreads();

    const float4* xv4 = (const float4*)xv;
    // f_v: warp-per-output, dot length 768 (192 float4, 6 per lane)
    for (int i = warp; i < 128; i += 8) {
        const float4* w = (const float4*)(W1v + i * 768);
        float s = 0.f;
#pragma unroll
        for (int q = 0; q < 6; q++)
            s += dot4(__ldg(w + lane + 32 * q), xv4[lane + 32 * q]);
        s = warpsum(s);
        if (lane == 0) xc[i] = eluf(s + b1v[i]);
    }
    // f_m: tiny (input dim 2)
    if (tid < 128)
        xc[128 + tid] = eluf(ma * W1m[tid * 2] + mb * W1m[tid * 2 + 1] + b1m[tid]);
    __syncthreads();

    // pre_low[t][g] = Wih_low[g, 0:256] . xcat + bih_low[g]
    const float4* xc4 = (const float4*)xc;
    for (int g = warp; g < 768; g += 8) {
        const float4* w = (const float4*)(WihL + g * 512);  // cols 0..255
        float s = dot4(__ldg(w + lane), xc4[lane]) +
                  dot4(__ldg(w + lane + 32), xc4[lane + 32]);
        s = warpsum(s);
        if (lane == 0) g_pre[t * 768 + g] = s + bihL[g];
    }

    // zero scan state + barrier (kernel boundary makes this visible to k2)
    if (blockIdx.x == 0) {
        if (tid < 256) { g_h1[0][tid] = 0.f; g_h2[tid] = 0.f; }
        if (tid == 0) g_bar = 0u;
    }
}

// ---------------- kernel 2: sequential 2-cell GRU scan, cooperative ----------------
__global__ void __launch_bounds__(256, 1) k2_scan(
    const float* __restrict__ WihL,   // (768,512) — cols 256..511 used here
    const float* __restrict__ WhhL,   // (768,256)
    const float* __restrict__ bhhL_g, // (768)
    const float* __restrict__ WihH,   // (768,256)
    const float* __restrict__ WhhH,   // (768,256)
    const float* __restrict__ bihH_g, // (768)
    const float* __restrict__ bhhH_g) // (768)
{
    // Block owns j in [j0, j0+4). Phase A dots (d = jj*9 + m*3 + r):
    //   m=0: Wih_low[j+256r, 256:512] . h2   (gi, h2 part)
    //   m=1: Whh_low[j+256r, :]       . h1   (gh low)
    //   m=2: Whh_high[j+256r, :]      . h2   (gh high, consumed in phase B)
    __shared__ __align__(16) float wA[36 * 256];
    __shared__ float dotsA[36], dotsB[12], preT[12], bhhL[12], bihH[12], bhhH[12];

    int tid = threadIdx.x, warp = tid >> 5, lane = tid & 31;
    int j0 = blockIdx.x * 4;

    // one-time weight stage into smem
    for (int d = 0; d < 36; d++) {
        int jj = d / 9, rem = d % 9, m = rem / 3, r = rem % 3;
        int row = j0 + jj + 256 * r;
        const float* src = (m == 0) ? (WihL + row * 512 + 256)
                         : (m == 1) ? (WhhL + row * 256)
                                    : (WhhH + row * 256);
        wA[d * 256 + tid] = src[tid];
    }
    if (tid < 12) {
        int jj = tid / 3, r = tid % 3, row = j0 + jj + 256 * r;
        bhhL[tid] = bhhL_g[row];
        bihH[tid] = bihH_g[row];
        bhhH[tid] = bhhH_g[row];
    }
    __syncthreads();

    unsigned phase = 0;
    for (int t = 0; t < T_STEPS; t++) {
        const float* h1r = g_h1[t & 1];
        float*       h1w = g_h1[(t & 1) ^ 1];

        if (tid < 12) {
            int jj = tid / 3, r = tid % 3;
            preT[tid] = __ldg(&g_pre[t * 768 + j0 + jj + 256 * r]);
        }
        // each lane's fixed x-chunks (elements [4l..4l+3] and [128+4l..128+4l+3])
        float4 h1a = __ldcg((const float4*)h1r + lane);
        float4 h1b = __ldcg((const float4*)h1r + lane + 32);
        float4 h2a = __ldcg((const float4*)g_h2 + lane);
        float4 h2b = __ldcg((const float4*)g_h2 + lane + 32);

        // ---- phase A: all old-state matvecs (warp-per-dot, smem weights) ----
        for (int d = warp; d < 36; d += 8) {
            int m = (d % 9) / 3;
            const float4* w = (const float4*)(wA + d * 256);
            float4 xa = (m == 1) ? h1a : h2a;
            float4 xb = (m == 1) ? h1b : h2b;
            float s = dot4(w[lane], xa) + dot4(w[lane + 32], xb);
            s = warpsum(s);
            if (lane == 0) dotsA[d] = s;
        }
        __syncthreads();

        if (tid < 4) {  // low-cell gate combine, fully local
            int jj = tid, j = j0 + jj;
            float gir = dotsA[jj * 9 + 0] + preT[jj * 3 + 0];
            float giz = dotsA[jj * 9 + 1] + preT[jj * 3 + 1];
            float gin = dotsA[jj * 9 + 2] + preT[jj * 3 + 2];
            float ghr = dotsA[jj * 9 + 3] + bhhL[jj * 3 + 0];
            float ghz = dotsA[jj * 9 + 4] + bhhL[jj * 3 + 1];
            float ghn = dotsA[jj * 9 + 5] + bhhL[jj * 3 + 2];
            float r_ = sigf(gir + ghr);
            float z_ = sigf(giz + ghz);
            float n_ = tanhf(gin + r_ * ghn);
            float h1o = __ldcg(h1r + j);
            float h1n = (1.f - z_) * n_ + z_ * h1o;
            h1w[j] = h1n;
            g_Lout[t * 256 + j] = h1n;
            __threadfence();  // release the h1 stores before arrival
        }
        // ---- grid barrier 1 ----
        phase++;
        __syncthreads();
        if (tid == 0) {
            asm volatile("red.release.gpu.global.add.u32 [%0], %1;"
                         :: "l"(&g_bar), "r"(1u) : "memory");
            unsigned target = phase * NB, v;
            do {
                asm volatile("ld.acquire.gpu.global.u32 %0, [%1];"
                             : "=r"(v) : "l"(&g_bar) : "memory");
            } while (v < target);
        }
        __syncthreads();

        // ---- phase B: Wih_high @ h1_new (weights from L2) ----
        float4 hna = __ldcg((const float4*)h1w + lane);
        float4 hnb = __ldcg((const float4*)h1w + lane + 32);
        for (int d = warp; d < 12; d += 8) {
            int jj = d / 3, r = d % 3, row = j0 + jj + 256 * r;
            const float4* w = (const float4*)(WihH + row * 256);
            float s = dot4(__ldg(w + lane), hna) + dot4(__ldg(w + lane + 32), hnb);
            s = warpsum(s);
            if (lane == 0) dotsB[d] = s + bihH[d];
        }
        __syncthreads();

        if (tid < 4) {  // high-cell gate combine
            int jj = tid, j = j0 + jj;
            float gir = dotsB[jj * 3 + 0];
            float giz = dotsB[jj * 3 + 1];
            float gin = dotsB[jj * 3 + 2];
            float ghr = dotsA[jj * 9 + 6] + bhhH[jj * 3 + 0];
            float ghz = dotsA[jj * 9 + 7] + bhhH[jj * 3 + 1];
            float ghn = dotsA[jj * 9 + 8] + bhhH[jj * 3 + 2];
            float r_ = sigf(gir + ghr);
            float z_ = sigf(giz + ghz);
            float n_ = tanhf(gin + r_ * ghn);
            float h2o = __ldcg(g_h2 + j);
            float h2n = (1.f - z_) * n_ + z_ * h2o;
            g_h2[j] = h2n;
            __threadfence();
        }
        // ---- grid barrier 2 ----
        phase++;
        __syncthreads();
        if (tid == 0) {
            asm volatile("red.release.gpu.global.add.u32 [%0], %1;"
                         :: "l"(&g_bar), "r"(1u) : "memory");
            unsigned target = phase * NB, v;
            do {
                asm volatile("ld.acquire.gpu.global.u32 %0, [%1];"
                             : "=r"(v) : "l"(&g_bar) : "memory");
            } while (v < target);
        }
        __syncthreads();
    }
}

// ---------------- kernel 3: output heads ----------------
__global__ void __launch_bounds__(256) k3_out(
    const float* __restrict__ W2v, // (768,128)
    const float* __restrict__ b2v, // (768)
    const float* __restrict__ W2m, // (2,128)
    const float* __restrict__ b2m, // (2)
    float* __restrict__ out)       // v_n (50*768) then m_n (50*2)
{
    int t = blockIdx.x, tid = threadIdx.x, warp = tid >> 5, lane = tid & 31;
    __shared__ __align__(16) float fv[128], fm[128];
    if (tid < 128) fv[tid] = eluf(g_Lout[t * 256 + tid]);
    else           fm[tid - 128] = eluf(g_Lout[t * 256 + tid]);
    __syncthreads();

    const float4* fv4 = (const float4*)fv;
    for (int i = warp; i < 768; i += 8) {
        float s = dot4(__ldg((const float4*)(W2v + i * 128) + lane), fv4[lane]);
        s = warpsum(s);
        if (lane == 0) out[t * 768 + i] = sigf(s + b2v[i]);
    }
    if (warp < 2) {
        const float4* fm4 = (const float4*)fm;
        float s = dot4(__ldg((const float4*)(W2m + warp * 128) + lane), fm4[lane]);
        s = warpsum(s);
        if (lane == 0) out[T_STEPS * 768 + t * 2 + warp] = tanhf(s + b2m[warp]);
    }
}

// ---------------- launch ----------------
extern "C" void kernel_launch(void* const* d_in, const int* in_sizes, int n_in,
                              void* d_out, int out_size) {
    const float* v0   = (const float*)d_in[0];
    const float* m0   = (const float*)d_in[1];
    const float* W1v  = (const float*)d_in[2];
    const float* b1v  = (const float*)d_in[3];
    const float* W1m  = (const float*)d_in[4];
    const float* b1m  = (const float*)d_in[5];
    const float* WihL = (const float*)d_in[6];
    const float* WhhL = (const float*)d_in[7];
    const float* bihL = (const float*)d_in[8];
    const float* bhhL = (const float*)d_in[9];
    const float* WihH = (const float*)d_in[10];
    const float* WhhH = (const float*)d_in[11];
    const float* bihH = (const float*)d_in[12];
    const float* bhhH = (const float*)d_in[13];
    const float* W2v  = (const float*)d_in[14];
    const float* b2v  = (const float*)d_in[15];
    const float* W2m  = (const float*)d_in[16];
    const float* b2m  = (const float*)d_in[17];
    float* out = (float*)d_out;

    k1_front<<<T_STEPS, 256>>>(v0, m0, W1v, b1v, W1m, b1m, WihL, bihL);
    k2_scan<<<NB, 256>>>(WihL, WhhL, bhhL, WihH, WhhH, bihH, bhhH);
    k3_out<<<T_STEPS, 256>>>(W2v, b2v, W2m, b2m, out);
}

// round 4
// speedup vs baseline: 1.0802x; 1.0802x over previous
#include <cuda_runtime.h>

#define T_STEPS 50
#define NB2 32          // scan CTAs; each owns 8 of 256 hidden units
#define HPER 8

// ---------------- scratch (device globals; no allocation) ----------------
__device__ float    g_pre[T_STEPS * 768];   // Wih_low[:, :256]@x_t + bih_low
__device__ float    g_xc [T_STEPS * 256];   // concat(f_v, f_m)
__device__ float    g_Lout[T_STEPS * 256];  // h1 per step
__device__ float    g_h1[2][256];           // double-buffered low state
__device__ float    g_h2[2][256];           // double-buffered high state
__device__ unsigned g_slots[NB2];           // per-CTA epoch barrier slots

// ---------------- helpers ----------------
__device__ __forceinline__ float warpsum(float v) {
    v += __shfl_xor_sync(0xffffffffu, v, 16);
    v += __shfl_xor_sync(0xffffffffu, v, 8);
    v += __shfl_xor_sync(0xffffffffu, v, 4);
    v += __shfl_xor_sync(0xffffffffu, v, 2);
    v += __shfl_xor_sync(0xffffffffu, v, 1);
    return v;
}
__device__ __forceinline__ float eluf(float x) { return x > 0.f ? x : expm1f(x); }
__device__ __forceinline__ float sigf(float x) { return 1.f / (1.f + expf(-x)); }
__device__ __forceinline__ float dot4(float4 a, float4 b) {
    return a.x * b.x + a.y * b.y + a.z * b.z + a.w * b.w;
}

// Epoch barrier: no atomics. Each CTA release-stores its epoch into its own
// slot; warp 0 polls all NB2 slots (one coalesced line) until all reach epoch.
__device__ __forceinline__ void gridbar(unsigned epoch, int tid, int cta) {
    __syncthreads();                     // all local stores done
    if (tid == 0)
        asm volatile("st.release.gpu.global.u32 [%0], %1;"
                     :: "l"(g_slots + cta), "r"(epoch) : "memory");
    if (tid < 32) {
        unsigned v;
        do {
            asm volatile("ld.acquire.gpu.global.u32 %0, [%1];"
                         : "=r"(v) : "l"(g_slots + tid) : "memory");
        } while (__any_sync(0xffffffffu, v < epoch));
    }
    __syncthreads();                     // release waiting threads
}

// ---------------- k1a: f_v / f_m -> g_xc, + state/slot init ----------------
__global__ void __launch_bounds__(256) k1a_feat(
    const float* __restrict__ v0, const float* __restrict__ m0,
    const float* __restrict__ W1v, const float* __restrict__ b1v,
    const float* __restrict__ W1m, const float* __restrict__ b1m)
{
    int t = blockIdx.x, half = blockIdx.y;
    int tid = threadIdx.x, warp = tid >> 5, lane = tid & 31;
    __shared__ __align__(16) float xv[768];
    for (int i = tid; i < 768; i += 256) xv[i] = v0[t * 768 + i];
    __syncthreads();

    const float4* xv4 = (const float4*)xv;
#pragma unroll
    for (int b = 0; b < 2; b++) {
        float p[4];
#pragma unroll
        for (int u = 0; u < 4; u++) {
            int i = half * 64 + warp + 8 * (b * 4 + u);
            const float4* w = (const float4*)(W1v + i * 768);
            float s = 0.f;
#pragma unroll
            for (int q = 0; q < 6; q++)
                s += dot4(__ldg(w + lane + 32 * q), xv4[lane + 32 * q]);
            p[u] = s;
        }
#pragma unroll
        for (int u = 0; u < 4; u++) {
            p[u] = warpsum(p[u]);
            int i = half * 64 + warp + 8 * (b * 4 + u);
            if (lane == 0) g_xc[t * 256 + i] = eluf(p[u] + b1v[i]);
        }
    }
    if (half == 1 && tid < 128) {
        float ma = m0[t * 2 + 0], mb = m0[t * 2 + 1];
        g_xc[t * 256 + 128 + tid] =
            eluf(ma * W1m[tid * 2] + mb * W1m[tid * 2 + 1] + b1m[tid]);
    }
    if (t == 0 && half == 0) {
        if (tid < 256) {
            g_h1[0][tid] = 0.f; g_h1[1][tid] = 0.f;
            g_h2[0][tid] = 0.f; g_h2[1][tid] = 0.f;
        }
        if (tid < NB2) g_slots[tid] = 0u;
    }
}

// ---------------- k1b: pre_low = WihL[:, :256] @ xc + bihL ----------------
__global__ void __launch_bounds__(256) k1b_pre(
    const float* __restrict__ WihL, const float* __restrict__ bihL)
{
    int t = blockIdx.x, s = blockIdx.y;
    int tid = threadIdx.x, warp = tid >> 5, lane = tid & 31;
    __shared__ __align__(16) float xc[256];
    if (tid < 256) xc[tid] = g_xc[t * 256 + tid];
    __syncthreads();
    const float4* xc4 = (const float4*)xc;

#pragma unroll
    for (int b = 0; b < 4; b++) {
        float p[6];
#pragma unroll
        for (int u = 0; u < 6; u++) {
            int g = s * 192 + warp + 8 * (b * 6 + u);
            const float4* w = (const float4*)(WihL + g * 512);  // cols 0..255
            p[u] = dot4(__ldg(w + lane), xc4[lane]) +
                   dot4(__ldg(w + lane + 32), xc4[lane + 32]);
        }
#pragma unroll
        for (int u = 0; u < 6; u++) {
            p[u] = warpsum(p[u]);
            int g = s * 192 + warp + 8 * (b * 6 + u);
            if (lane == 0) g_pre[t * 768 + g] = p[u] + bihL[g];
        }
    }
}

// ---------------- k2: cooperative 2-cell GRU scan ----------------
// Dynamic smem: wA[48][256] (phase A rows), wB[48][256] (phase B rows).
// Phase A rows (d = warp + 8*i): i<3 -> WihL[grow, 256:512] (x=h2_old),
//                                i>=3 -> WhhL[grow]          (x=h1_old).
// Phase B rows:                  i<3 -> WihH[grow] (x=h1_new),
//                                i>=3 -> WhhH[grow] (x=h2_old).
extern __shared__ float smw[];
__global__ void __launch_bounds__(256, 1) k2_scan(
    const float* __restrict__ WihL, const float* __restrict__ WhhL,
    const float* __restrict__ bhhLg,
    const float* __restrict__ WihH, const float* __restrict__ WhhH,
    const float* __restrict__ bihHg, const float* __restrict__ bhhHg)
{
    float* wA = smw;
    float* wB = smw + 48 * 256;
    __shared__ float dots[48], preS[24], bA[24], bB1[24], bB2[24];

    int tid = threadIdx.x, warp = tid >> 5, lane = tid & 31, cta = blockIdx.x;
    int j0 = cta * HPER;

    // one-time weight stage (4 rows per iteration, 64 float4 per row)
    {
        int r4 = tid >> 6, c = tid & 63;
        for (int d0 = 0; d0 < 48; d0 += 4) {
            int d = d0 + r4;
            int jj = (d % 24) / 3, r = d % 3, grow = j0 + jj + 256 * r;
            const float4* srcA = (d < 24)
                ? (const float4*)(WihL + grow * 512 + 256)
                : (const float4*)(WhhL + grow * 256);
            ((float4*)(wA + d * 256))[c] = __ldg(srcA + c);
            const float4* srcB = (d < 24)
                ? (const float4*)(WihH + grow * 256)
                : (const float4*)(WhhH + grow * 256);
            ((float4*)(wB + d * 256))[c] = __ldg(srcB + c);
        }
    }
    if (tid < 24) {
        int jj = tid / 3, r = tid % 3, grow = j0 + jj + 256 * r;
        bA[tid]  = bhhLg[grow];
        bB1[tid] = bihHg[grow];
        bB2[tid] = bhhHg[grow];
    }
    __syncthreads();

    for (int t = 0; t < T_STEPS; t++) {
        if (tid < 24)
            preS[tid] = __ldg(&g_pre[t * 768 + j0 + (tid / 3) + 256 * (tid % 3)]);

        const float* h1r = g_h1[t & 1];
        const float* h2r = g_h2[t & 1];
        float*       h1w = g_h1[(t & 1) ^ 1];
        float*       h2w = g_h2[(t & 1) ^ 1];
        float4 h1a = __ldcg((const float4*)h1r + lane);
        float4 h1b = __ldcg((const float4*)h1r + lane + 32);
        float4 h2a = __ldcg((const float4*)h2r + lane);
        float4 h2b = __ldcg((const float4*)h2r + lane + 32);

        // ---- phase A ----
        {
            float p[6];
#pragma unroll
            for (int i = 0; i < 6; i++) {
                int d = warp + 8 * i;
                const float4* w = (const float4*)(wA + d * 256);
                float4 xa = (i < 3) ? h2a : h1a;
                float4 xb = (i < 3) ? h2b : h1b;
                p[i] = dot4(w[lane], xa) + dot4(w[lane + 32], xb);
            }
#pragma unroll
            for (int i = 0; i < 6; i++) p[i] = warpsum(p[i]);
            if (lane == 0) {
#pragma unroll
                for (int i = 0; i < 6; i++) dots[warp + 8 * i] = p[i];
            }
        }
        __syncthreads();
        if (tid < HPER) {
            int jj = tid, j = j0 + jj;
            float gir = preS[jj * 3 + 0] + dots[jj * 3 + 0];
            float giz = preS[jj * 3 + 1] + dots[jj * 3 + 1];
            float gin = preS[jj * 3 + 2] + dots[jj * 3 + 2];
            float ghr = dots[24 + jj * 3 + 0] + bA[jj * 3 + 0];
            float ghz = dots[24 + jj * 3 + 1] + bA[jj * 3 + 1];
            float ghn = dots[24 + jj * 3 + 2] + bA[jj * 3 + 2];
            float r_ = sigf(gir + ghr);
            float z_ = sigf(giz + ghz);
            float n_ = tanhf(gin + r_ * ghn);
            float h1n = (1.f - z_) * n_ + z_ * __ldcg(h1r + j);
            h1w[j] = h1n;
            g_Lout[t * 256 + j] = h1n;
        }
        if (t == T_STEPS - 1) break;   // h2(t_last+1) unused; skip phase B
        gridbar(2 * t + 1, tid, cta);

        // ---- phase B ----
        float4 na = __ldcg((const float4*)h1w + lane);
        float4 nb = __ldcg((const float4*)h1w + lane + 32);
        {
            float p[6];
#pragma unroll
            for (int i = 0; i < 6; i++) {
                int d = warp + 8 * i;
                const float4* w = (const float4*)(wB + d * 256);
                float4 xa = (i < 3) ? na : h2a;
                float4 xb = (i < 3) ? nb : h2b;
                p[i] = dot4(w[lane], xa) + dot4(w[lane + 32], xb);
            }
#pragma unroll
            for (int i = 0; i < 6; i++) p[i] = warpsum(p[i]);
            if (lane == 0) {
#pragma unroll
                for (int i = 0; i < 6; i++) dots[warp + 8 * i] = p[i];
            }
        }
        __syncthreads();
        if (tid < HPER) {
            int jj = tid, j = j0 + jj;
            float gir = dots[jj * 3 + 0] + bB1[jj * 3 + 0];
            float giz = dots[jj * 3 + 1] + bB1[jj * 3 + 1];
            float gin = dots[jj * 3 + 2] + bB1[jj * 3 + 2];
            float ghr = dots[24 + jj * 3 + 0] + bB2[jj * 3 + 0];
            float ghz = dots[24 + jj * 3 + 1] + bB2[jj * 3 + 1];
            float ghn = dots[24 + jj * 3 + 2] + bB2[jj * 3 + 2];
            float r_ = sigf(gir + ghr);
            float z_ = sigf(giz + ghz);
            float n_ = tanhf(gin + r_ * ghn);
            h2w[j] = (1.f - z_) * n_ + z_ * __ldcg(h2r + j);
        }
        gridbar(2 * t + 2, tid, cta);
    }
}

// ---------------- k3: output heads ----------------
__global__ void __launch_bounds__(256) k3_out(
    const float* __restrict__ W2v, const float* __restrict__ b2v,
    const float* __restrict__ W2m, const float* __restrict__ b2m,
    float* __restrict__ out)
{
    int t = blockIdx.x, s = blockIdx.y;
    int tid = threadIdx.x, warp = tid >> 5, lane = tid & 31;
    __shared__ __align__(16) float fv[128], fm[128];
    if (tid < 128) fv[tid] = eluf(g_Lout[t * 256 + tid]);
    else           fm[tid - 128] = eluf(g_Lout[t * 256 + tid]);
    __syncthreads();

    const float4* fv4 = (const float4*)fv;
#pragma unroll
    for (int b = 0; b < 6; b++) {
        float p[8];
#pragma unroll
        for (int u = 0; u < 8; u++) {
            int i = s * 384 + warp + 8 * (b * 8 + u);
            p[u] = dot4(__ldg((const float4*)(W2v + i * 128) + lane), fv4[lane]);
        }
#pragma unroll
        for (int u = 0; u < 8; u++) {
            p[u] = warpsum(p[u]);
            int i = s * 384 + warp + 8 * (b * 8 + u);
            if (lane == 0) out[t * 768 + i] = sigf(p[u] + b2v[i]);
        }
    }
    if (s == 1 && warp < 2) {
        const float4* fm4 = (const float4*)fm;
        float v = dot4(__ldg((const float4*)(W2m + warp * 128) + lane), fm4[lane]);
        v = warpsum(v);
        if (lane == 0) out[T_STEPS * 768 + t * 2 + warp] = tanhf(v + b2m[warp]);
    }
}

// ---------------- launch ----------------
extern "C" void kernel_launch(void* const* d_in, const int* in_sizes, int n_in,
                              void* d_out, int out_size) {
    const float* v0   = (const float*)d_in[0];
    const float* m0   = (const float*)d_in[1];
    const float* W1v  = (const float*)d_in[2];
    const float* b1v  = (const float*)d_in[3];
    const float* W1m  = (const float*)d_in[4];
    const float* b1m  = (const float*)d_in[5];
    const float* WihL = (const float*)d_in[6];
    const float* WhhL = (const float*)d_in[7];
    const float* bihL = (const float*)d_in[8];
    const float* bhhL = (const float*)d_in[9];
    const float* WihH = (const float*)d_in[10];
    const float* WhhH = (const float*)d_in[11];
    const float* bihH = (const float*)d_in[12];
    const float* bhhH = (const float*)d_in[13];
    const float* W2v  = (const float*)d_in[14];
    const float* b2v  = (const float*)d_in[15];
    const float* W2m  = (const float*)d_in[16];
    const float* b2m  = (const float*)d_in[17];
    float* out = (float*)d_out;

    const int K2_SMEM = 96 * 256 * 4;  // 98304 B dynamic
    cudaFuncSetAttribute(k2_scan, cudaFuncAttributeMaxDynamicSharedMemorySize,
                         K2_SMEM);

    k1a_feat<<<dim3(T_STEPS, 2), 256>>>(v0, m0, W1v, b1v, W1m, b1m);
    k1b_pre <<<dim3(T_STEPS, 4), 256>>>(WihL, bihL);
    k2_scan <<<NB2, 256, K2_SMEM>>>(WihL, WhhL, bhhL, WihH, WhhH, bihH, bhhH);
    k3_out  <<<dim3(T_STEPS, 2), 256>>>(W2v, b2v, W2m, b2m, out);
}

// round 5
// speedup vs baseline: 1.3170x; 1.2193x over previous
#include <cuda_runtime.h>
#include <cstdint>

#define T_STEPS 50
#define NB2 32          // fallback scan CTAs
#define CL 16           // cluster CTAs; each owns 16 of 256 hidden units

// ---------------- scratch (device globals; no allocation) ----------------
__device__ float    g_pre[T_STEPS * 768];   // Wih_low[:, :256]@x_t + bih_low
__device__ float    g_xc [T_STEPS * 256];   // concat(f_v, f_m)
__device__ float    g_Lout[T_STEPS * 256];  // h1 per step
__device__ float    g_h1[2][256];           // fallback state
__device__ float    g_h2[2][256];
__device__ unsigned g_slots[NB2];           // fallback barrier slots

// ---------------- helpers ----------------
__device__ __forceinline__ float warpsum(float v) {
    v += __shfl_xor_sync(0xffffffffu, v, 16);
    v += __shfl_xor_sync(0xffffffffu, v, 8);
    v += __shfl_xor_sync(0xffffffffu, v, 4);
    v += __shfl_xor_sync(0xffffffffu, v, 2);
    v += __shfl_xor_sync(0xffffffffu, v, 1);
    return v;
}
__device__ __forceinline__ float eluf(float x) { return x > 0.f ? x : expm1f(x); }
__device__ __forceinline__ float sigf(float x) { return 1.f / (1.f + expf(-x)); }
__device__ __forceinline__ float dot4(float4 a, float4 b) {
    return a.x * b.x + a.y * b.y + a.z * b.z + a.w * b.w;
}
__device__ __forceinline__ uint32_t s2u(const void* p) {
    uint32_t a;
    asm("{ .reg .u64 t; cvta.to.shared.u64 t, %1; cvt.u32.u64 %0, t; }"
        : "=r"(a) : "l"(p));
    return a;
}

// fallback epoch barrier (round-3, proven)
__device__ __forceinline__ void gridbar(unsigned epoch, int tid, int cta) {
    __syncthreads();
    if (tid == 0)
        asm volatile("st.release.gpu.global.u32 [%0], %1;"
                     :: "l"(g_slots + cta), "r"(epoch) : "memory");
    if (tid < 32) {
        unsigned v;
        do {
            asm volatile("ld.acquire.gpu.global.u32 %0, [%1];"
                         : "=r"(v) : "l"(g_slots + tid) : "memory");
        } while (__any_sync(0xffffffffu, v < epoch));
    }
    __syncthreads();
}

#define CLUSTER_ARRIVE() asm volatile("barrier.cluster.arrive.aligned;" ::: "memory")
#define CLUSTER_WAIT()   asm volatile("barrier.cluster.wait.aligned;" ::: "memory")

// broadcast one float into h-array slot j of every cluster CTA's smem
__device__ __forceinline__ void bcast16(uint32_t laddr, float v) {
#pragma unroll
    for (int rk = 0; rk < CL; rk++) {
        uint32_t ra;
        asm volatile("mapa.shared::cluster.u32 %0, %1, %2;"
                     : "=r"(ra) : "r"(laddr), "r"(rk));
        asm volatile("st.shared::cluster.f32 [%0], %1;"
                     :: "r"(ra), "f"(v) : "memory");
    }
}

// ---------------- k1a: f_v / f_m -> g_xc, + fallback state init ----------------
__global__ void __launch_bounds__(256) k1a_feat(
    const float* __restrict__ v0, const float* __restrict__ m0,
    const float* __restrict__ W1v, const float* __restrict__ b1v,
    const float* __restrict__ W1m, const float* __restrict__ b1m)
{
    int t = blockIdx.x, q = blockIdx.y;
    int tid = threadIdx.x, warp = tid >> 5, lane = tid & 31;
    __shared__ __align__(16) float xv[768];
    for (int i = tid; i < 768; i += 256) xv[i] = v0[t * 768 + i];
    __syncthreads();

    const float4* xv4 = (const float4*)xv;
    float p[4];
#pragma unroll
    for (int u = 0; u < 4; u++) {
        int i = q * 32 + warp + 8 * u;
        const float4* w = (const float4*)(W1v + i * 768);
        float s = 0.f;
#pragma unroll
        for (int k = 0; k < 6; k++)
            s += dot4(__ldg(w + lane + 32 * k), xv4[lane + 32 * k]);
        p[u] = s;
    }
#pragma unroll
    for (int u = 0; u < 4; u++) {
        p[u] = warpsum(p[u]);
        int i = q * 32 + warp + 8 * u;
        if (lane == 0) g_xc[t * 256 + i] = eluf(p[u] + b1v[i]);
    }
    if (q == 0 && tid < 128) {
        float ma = m0[t * 2 + 0], mb = m0[t * 2 + 1];
        g_xc[t * 256 + 128 + tid] =
            eluf(ma * W1m[tid * 2] + mb * W1m[tid * 2 + 1] + b1m[tid]);
    }
    if (t == 0 && q == 0) {   // fallback-path state (harmless otherwise)
        if (tid < 256) {
            g_h1[0][tid] = 0.f; g_h1[1][tid] = 0.f;
            g_h2[0][tid] = 0.f; g_h2[1][tid] = 0.f;
        }
        if (tid < NB2) g_slots[tid] = 0u;
    }
}

// ---------------- k1b: pre_low = WihL[:, :256] @ xc + bihL ----------------
__global__ void __launch_bounds__(256) k1b_pre(
    const float* __restrict__ WihL, const float* __restrict__ bihL)
{
    int t = blockIdx.x, s = blockIdx.y;
    int tid = threadIdx.x, warp = tid >> 5, lane = tid & 31;
    __shared__ __align__(16) float xc[256];
    if (tid < 256) xc[tid] = g_xc[t * 256 + tid];
    __syncthreads();
    const float4* xc4 = (const float4*)xc;

#pragma unroll
    for (int b = 0; b < 4; b++) {
        float p[4];
#pragma unroll
        for (int u = 0; u < 4; u++) {
            int g = s * 128 + warp + 8 * (b * 4 + u);
            const float4* w = (const float4*)(WihL + g * 512);
            p[u] = dot4(__ldg(w + lane), xc4[lane]) +
                   dot4(__ldg(w + lane + 32), xc4[lane + 32]);
        }
#pragma unroll
        for (int u = 0; u < 4; u++) {
            p[u] = warpsum(p[u]);
            int g = s * 128 + warp + 8 * (b * 4 + u);
            if (lane == 0) g_pre[t * 768 + g] = p[u] + bihL[g];
        }
    }
}

// ================== k2 cluster version: 16-CTA DSMEM scan ==================
// Dot index d (0..95 per phase) = jj*6 + r*2 + m  (jj: unit 0..15, r: gate, m: matrix)
// phase A: m=0 -> WihL[row,256:512] . h2_old ; m=1 -> WhhL[row] . h1_old
// phase B: m=0 -> WihH[row]         . h1_new ; m=1 -> WhhH[row] . h2_old
// Warp w, lane-group g(=lane>>3): per pass d = w*12 + it*4 + g, note d&1 == g&1 == m.
extern __shared__ float smw[];  // [2][96][256] weights: A then B
__global__ void __launch_bounds__(256, 1) k2_cluster(
    const float* __restrict__ WihL, const float* __restrict__ WhhL,
    const float* __restrict__ bhhLg,
    const float* __restrict__ WihH, const float* __restrict__ WhhH,
    const float* __restrict__ bihHg, const float* __restrict__ bhhHg)
{
    __shared__ __align__(16) float h1s[2][256], h2s[2][256];
    __shared__ float dots[96], preS[48], sbhhL[48], sbihH[48], sbhhH[48];

    int tid = threadIdx.x, warp = tid >> 5, lane = tid & 31;
    int grp = lane >> 3, l = lane & 7, m = grp & 1;
    uint32_t rank;
    asm("mov.u32 %0, %%cluster_ctarank;" : "=r"(rank));
    int j0 = (int)rank * 16;

    // ---- one-time weight stage: 192 rows x 64 float4 ----
    {
        int rsel = tid >> 6, c = tid & 63;
        for (int d0 = 0; d0 < 192; d0 += 4) {
            int d = d0 + rsel;
            int dd = (d < 96) ? d : d - 96;
            int jj = dd / 6, rm = dd % 6, r = rm >> 1, mm = rm & 1;
            int row = j0 + jj + 256 * r;
            const float4* src;
            if (d < 96)
                src = mm ? (const float4*)(WhhL + row * 256)
                         : (const float4*)(WihL + row * 512 + 256);
            else
                src = mm ? (const float4*)(WhhH + row * 256)
                         : (const float4*)(WihH + row * 256);
            ((float4*)(smw + d * 256))[c] = __ldg(src + c);
        }
    }
    if (tid < 48) {
        int jj = tid / 3, r = tid % 3, row = j0 + jj + 256 * r;
        sbhhL[tid] = bhhLg[row];
        sbihH[tid] = bihHg[row];
        sbhhH[tid] = bhhHg[row];
        preS[tid]  = g_pre[0 * 768 + jj + 256 * r + j0];
    }
    if (tid < 256) { h1s[0][tid] = 0.f; h2s[0][tid] = 0.f; }
    __syncthreads();
    CLUSTER_ARRIVE(); CLUSTER_WAIT();

    for (int t = 0; t < T_STEPS; t++) {
        int cb = t & 1, nb = cb ^ 1;

        // ---- phase A: gates of h1_new ----
        {
            const float4* xp = (const float4*)(m ? h1s[cb] : h2s[cb]);
            float4 xq[8];
#pragma unroll
            for (int qq = 0; qq < 8; qq++) xq[qq] = xp[l + 8 * qq];
#pragma unroll
            for (int it = 0; it < 3; it++) {
                int d = warp * 12 + it * 4 + grp;
                const float4* wr = (const float4*)(smw + d * 256);
                float a = 0.f;
#pragma unroll
                for (int qq = 0; qq < 8; qq++) a += dot4(wr[l + 8 * qq], xq[qq]);
                a += __shfl_xor_sync(0xffffffffu, a, 1);
                a += __shfl_xor_sync(0xffffffffu, a, 2);
                a += __shfl_xor_sync(0xffffffffu, a, 4);
                if (l == 0) dots[d] = a;
            }
        }
        __syncthreads();
        if (tid < 16) {
            int jj = tid, j = j0 + jj;
            float r_ = sigf(preS[jj * 3 + 0] + dots[jj * 6 + 0] +
                            dots[jj * 6 + 1] + sbhhL[jj * 3 + 0]);
            float z_ = sigf(preS[jj * 3 + 1] + dots[jj * 6 + 2] +
                            dots[jj * 6 + 3] + sbhhL[jj * 3 + 1]);
            float n_ = tanhf(preS[jj * 3 + 2] + dots[jj * 6 + 4] +
                             r_ * (dots[jj * 6 + 5] + sbhhL[jj * 3 + 2]));
            float h1n = (1.f - z_) * n_ + z_ * h1s[cb][j];
            g_Lout[t * 256 + j] = h1n;
            if (t < T_STEPS - 1) bcast16(s2u(&h1s[nb][j]), h1n);
        }
        if (t == T_STEPS - 1) break;     // h2 beyond last step unused
        CLUSTER_ARRIVE(); CLUSTER_WAIT();

        // ---- phase B: gates of h2_new (reads h1s[nb]) ----
        {
            const float4* xp = (const float4*)(m ? h2s[cb] : h1s[nb]);
            float4 xq[8];
#pragma unroll
            for (int qq = 0; qq < 8; qq++) xq[qq] = xp[l + 8 * qq];
#pragma unroll
            for (int it = 0; it < 3; it++) {
                int d = warp * 12 + it * 4 + grp;
                const float4* wr = (const float4*)(smw + (96 + d) * 256);
                float a = 0.f;
#pragma unroll
                for (int qq = 0; qq < 8; qq++) a += dot4(wr[l + 8 * qq], xq[qq]);
                a += __shfl_xor_sync(0xffffffffu, a, 1);
                a += __shfl_xor_sync(0xffffffffu, a, 2);
                a += __shfl_xor_sync(0xffffffffu, a, 4);
                if (l == 0) dots[d] = a;
            }
        }
        __syncthreads();
        if (tid < 16) {
            int jj = tid, j = j0 + jj;
            float r_ = sigf(dots[jj * 6 + 0] + sbihH[jj * 3 + 0] +
                            dots[jj * 6 + 1] + sbhhH[jj * 3 + 0]);
            float z_ = sigf(dots[jj * 6 + 2] + sbihH[jj * 3 + 1] +
                            dots[jj * 6 + 3] + sbhhH[jj * 3 + 1]);
            float n_ = tanhf(dots[jj * 6 + 4] + sbihH[jj * 3 + 2] +
                             r_ * (dots[jj * 6 + 5] + sbhhH[jj * 3 + 2]));
            float h2n = (1.f - z_) * n_ + z_ * h2s[cb][j];
            bcast16(s2u(&h2s[nb][j]), h2n);
        }
        CLUSTER_ARRIVE();
        if (tid < 48)   // prefetch next step's pre during barrier wait
            preS[tid] = g_pre[(t + 1) * 768 + j0 + (tid / 3) + 256 * (tid % 3)];
        CLUSTER_WAIT();
    }
}

// ---------------- k2 fallback: round-3 L2-flag scan (proven) ----------------
__global__ void __launch_bounds__(256, 1) k2_scan(
    const float* __restrict__ WihL, const float* __restrict__ WhhL,
    const float* __restrict__ bhhLg,
    const float* __restrict__ WihH, const float* __restrict__ WhhH,
    const float* __restrict__ bihHg, const float* __restrict__ bhhHg)
{
    float* wA = smw;
    float* wB = smw + 48 * 256;
    __shared__ float dots[48], preS[24], bA[24], bB1[24], bB2[24];

    int tid = threadIdx.x, warp = tid >> 5, lane = tid & 31, cta = blockIdx.x;
    int j0 = cta * 8;
    {
        int r4 = tid >> 6, c = tid & 63;
        for (int d0 = 0; d0 < 48; d0 += 4) {
            int d = d0 + r4;
            int jj = (d % 24) / 3, r = d % 3, grow = j0 + jj + 256 * r;
            const float4* srcA = (d < 24)
                ? (const float4*)(WihL + grow * 512 + 256)
                : (const float4*)(WhhL + grow * 256);
            ((float4*)(wA + d * 256))[c] = __ldg(srcA + c);
            const float4* srcB = (d < 24)
                ? (const float4*)(WihH + grow * 256)
                : (const float4*)(WhhH + grow * 256);
            ((float4*)(wB + d * 256))[c] = __ldg(srcB + c);
        }
    }
    if (tid < 24) {
        int jj = tid / 3, r = tid % 3, grow = j0 + jj + 256 * r;
        bA[tid] = bhhLg[grow]; bB1[tid] = bihHg[grow]; bB2[tid] = bhhHg[grow];
    }
    __syncthreads();

    for (int t = 0; t < T_STEPS; t++) {
        if (tid < 24)
            preS[tid] = __ldg(&g_pre[t * 768 + j0 + (tid / 3) + 256 * (tid % 3)]);
        const float* h1r = g_h1[t & 1];
        const float* h2r = g_h2[t & 1];
        float* h1w = g_h1[(t & 1) ^ 1];
        float* h2w = g_h2[(t & 1) ^ 1];
        float4 h1a = __ldcg((const float4*)h1r + lane);
        float4 h1b = __ldcg((const float4*)h1r + lane + 32);
        float4 h2a = __ldcg((const float4*)h2r + lane);
        float4 h2b = __ldcg((const float4*)h2r + lane + 32);
        {
            float p[6];
#pragma unroll
            for (int i = 0; i < 6; i++) {
                const float4* w = (const float4*)(wA + (warp + 8 * i) * 256);
                float4 xa = (i < 3) ? h2a : h1a, xb = (i < 3) ? h2b : h1b;
                p[i] = dot4(w[lane], xa) + dot4(w[lane + 32], xb);
            }
#pragma unroll
            for (int i = 0; i < 6; i++) p[i] = warpsum(p[i]);
            if (lane == 0)
#pragma unroll
                for (int i = 0; i < 6; i++) dots[warp + 8 * i] = p[i];
        }
        __syncthreads();
        if (tid < 8) {
            int jj = tid, j = j0 + jj;
            float r_ = sigf(preS[jj*3+0] + dots[jj*3+0] + dots[24+jj*3+0] + bA[jj*3+0]);
            float z_ = sigf(preS[jj*3+1] + dots[jj*3+1] + dots[24+jj*3+1] + bA[jj*3+1]);
            float n_ = tanhf(preS[jj*3+2] + dots[jj*3+2] + r_*(dots[24+jj*3+2] + bA[jj*3+2]));
            float h1n = (1.f - z_) * n_ + z_ * __ldcg(h1r + j);
            h1w[j] = h1n;
            g_Lout[t * 256 + j] = h1n;
        }
        if (t == T_STEPS - 1) break;
        gridbar(2 * t + 1, tid, cta);
        float4 na = __ldcg((const float4*)h1w + lane);
        float4 nb4 = __ldcg((const float4*)h1w + lane + 32);
        {
            float p[6];
#pragma unroll
            for (int i = 0; i < 6; i++) {
                const float4* w = (const float4*)(wB + (warp + 8 * i) * 256);
                float4 xa = (i < 3) ? na : h2a, xb = (i < 3) ? nb4 : h2b;
                p[i] = dot4(w[lane], xa) + dot4(w[lane + 32], xb);
            }
#pragma unroll
            for (int i = 0; i < 6; i++) p[i] = warpsum(p[i]);
            if (lane == 0)
#pragma unroll
                for (int i = 0; i < 6; i++) dots[warp + 8 * i] = p[i];
        }
        __syncthreads();
        if (tid < 8) {
            int jj = tid, j = j0 + jj;
            float r_ = sigf(dots[jj*3+0] + bB1[jj*3+0] + dots[24+jj*3+0] + bB2[jj*3+0]);
            float z_ = sigf(dots[jj*3+1] + bB1[jj*3+1] + dots[24+jj*3+1] + bB2[jj*3+1]);
            float n_ = tanhf(dots[jj*3+2] + bB1[jj*3+2] + r_*(dots[24+jj*3+2] + bB2[jj*3+2]));
            h2w[j] = (1.f - z_) * n_ + z_ * __ldcg(h2r + j);
        }
        gridbar(2 * t + 2, tid, cta);
    }
}

// ---------------- k3: output heads ----------------
__global__ void __launch_bounds__(256) k3_out(
    const float* __restrict__ W2v, const float* __restrict__ b2v,
    const float* __restrict__ W2m, const float* __restrict__ b2m,
    float* __restrict__ out)
{
    int t = blockIdx.x, s = blockIdx.y;
    int tid = threadIdx.x, warp = tid >> 5, lane = tid & 31;
    __shared__ __align__(16) float fv[128], fm[128];
    if (tid < 128) fv[tid] = eluf(g_Lout[t * 256 + tid]);
    else           fm[tid - 128] = eluf(g_Lout[t * 256 + tid]);
    __syncthreads();

    const float4* fv4 = (const float4*)fv;
#pragma unroll
    for (int b = 0; b < 3; b++) {
        float p[8];
#pragma unroll
        for (int u = 0; u < 8; u++) {
            int i = s * 192 + warp + 8 * (b * 8 + u);
            p[u] = dot4(__ldg((const float4*)(W2v + i * 128) + lane), fv4[lane]);
        }
#pragma unroll
        for (int u = 0; u < 8; u++) {
            p[u] = warpsum(p[u]);
            int i = s * 192 + warp + 8 * (b * 8 + u);
            if (lane == 0) out[t * 768 + i] = sigf(p[u] + b2v[i]);
        }
    }
    if (s == 3 && warp < 2) {
        const float4* fm4 = (const float4*)fm;
        float v = dot4(__ldg((const float4*)(W2m + warp * 128) + lane), fm4[lane]);
        v = warpsum(v);
        if (lane == 0) out[T_STEPS * 768 + t * 2 + warp] = tanhf(v + b2m[warp]);
    }
}

// ---------------- launch ----------------
extern "C" void kernel_launch(void* const* d_in, const int* in_sizes, int n_in,
                              void* d_out, int out_size) {
    const float* v0   = (const float*)d_in[0];
    const float* m0   = (const float*)d_in[1];
    const float* W1v  = (const float*)d_in[2];
    const float* b1v  = (const float*)d_in[3];
    const float* W1m  = (const float*)d_in[4];
    const float* b1m  = (const float*)d_in[5];
    const float* WihL = (const float*)d_in[6];
    const float* WhhL = (const float*)d_in[7];
    const float* bihL = (const float*)d_in[8];
    const float* bhhL = (const float*)d_in[9];
    const float* WihH = (const float*)d_in[10];
    const float* WhhH = (const float*)d_in[11];
    const float* bihH = (const float*)d_in[12];
    const float* bhhH = (const float*)d_in[13];
    const float* W2v  = (const float*)d_in[14];
    const float* b2v  = (const float*)d_in[15];
    const float* W2m  = (const float*)d_in[16];
    const float* b2m  = (const float*)d_in[17];
    float* out = (float*)d_out;

    const int CL_SMEM = 192 * 256 * 4;  // 196608 B
    const int FB_SMEM = 96 * 256 * 4;   // 98304 B
    cudaFuncSetAttribute(k2_cluster, cudaFuncAttributeMaxDynamicSharedMemorySize, CL_SMEM);
    cudaFuncSetAttribute(k2_cluster, cudaFuncAttributeNonPortableClusterSizeAllowed, 1);
    cudaFuncSetAttribute(k2_scan, cudaFuncAttributeMaxDynamicSharedMemorySize, FB_SMEM);

    k1a_feat<<<dim3(T_STEPS, 4), 256>>>(v0, m0, W1v, b1v, W1m, b1m);
    k1b_pre <<<dim3(T_STEPS, 6), 256>>>(WihL, bihL);

    cudaLaunchConfig_t cfg = {};
    cfg.gridDim = dim3(CL, 1, 1);
    cfg.blockDim = dim3(256, 1, 1);
    cfg.dynamicSmemBytes = CL_SMEM;
    cfg.stream = 0;
    cudaLaunchAttribute attrs[1];
    attrs[0].id = cudaLaunchAttributeClusterDimension;
    attrs[0].val.clusterDim = {CL, 1, 1};
    cfg.attrs = attrs;
    cfg.numAttrs = 1;
    cudaError_t st = cudaLaunchKernelEx(&cfg, k2_cluster,
                                        WihL, WhhL, bhhL, WihH, WhhH, bihH, bhhH);
    if (st != cudaSuccess) {
        (void)cudaGetLastError();  // clear; deterministic fallback path
        k2_scan<<<NB2, 256, FB_SMEM>>>(WihL, WhhL, bhhL, WihH, WhhH, bihH, bhhH);
    }

    k3_out<<<dim3(T_STEPS, 4), 256>>>(W2v, b2v, W2m, b2m, out);
}